// round 6
// baseline (speedup 1.0000x reference)
#include <cuda_runtime.h>
#include <math.h>

#define SEQ 4096
#define DIM 1024
#define NH  16
#define HD  64
#define KT  32   // keys per flash tile

// ---------------- device scratch (no allocation allowed) ----------------
__device__ float g_qkv[SEQ * 3 * DIM];     // QKV projection output
__device__ float g_Q[NH * SEQ * HD];       // roped, head-major
__device__ float g_K[NH * SEQ * HD];
__device__ float g_V[NH * SEQ * HD];
__device__ float g_O[SEQ * DIM];           // attention output (s, dim)
__device__ float g_att[SEQ * DIM];         // after out-proj, pre-LN
__device__ float g_cos[SEQ * 512];
__device__ float g_sin[SEQ * 512];

// ---------------- TF32 helpers ------------------------------------------
__device__ __forceinline__ unsigned f2tf32(float x) {
    unsigned r;
    asm("cvt.rna.tf32.f32 %0, %1;" : "=r"(r) : "f"(x));
    return r;
}
__device__ __forceinline__ void mma_tf32(float* c, const unsigned* a, const unsigned* b) {
    asm volatile(
        "mma.sync.aligned.m16n8k8.row.col.f32.tf32.tf32.f32 "
        "{%0,%1,%2,%3}, {%4,%5,%6,%7}, {%8,%9}, {%0,%1,%2,%3};"
        : "+f"(c[0]), "+f"(c[1]), "+f"(c[2]), "+f"(c[3])
        : "r"(a[0]), "r"(a[1]), "r"(a[2]), "r"(a[3]), "r"(b[0]), "r"(b[1]));
}

// ---------------- RoPE tables (double precision for accurate trig) ------
__global__ void rope_tables_kernel() {
    int idx = blockIdx.x * blockDim.x + threadIdx.x;
    if (idx >= SEQ * 512) return;
    int s = idx >> 9;
    int i = idx & 511;
    float invf = (float)exp(-((double)i) * (9.210340371976184 / 512.0));
    double ang = (double)s * (double)invf;
    g_cos[idx] = (float)cos(ang);
    g_sin[idx] = (float)sin(ang);
}

// ---------------- RoPE apply + scatter to head-major Q/K/V --------------
__global__ void rope_scatter_kernel() {
    int idx = blockIdx.x * blockDim.x + threadIdx.x;   // SEQ*DIM threads
    int s = idx >> 10;
    int j = idx & 1023;
    int i = j & 511;
    float c  = g_cos[(s << 9) + i];
    float sn = g_sin[(s << 9) + i];
    const float* row = g_qkv + (size_t)s * (3 * DIM);
    float q = row[j];
    float k = row[DIM + j];
    float v = row[2 * DIM + j];
    float q2, k2;
    if (j < 512) { q2 = -row[j + 512];       k2 = -row[DIM + j + 512]; }
    else         { q2 =  row[j - 512];       k2 =  row[DIM + j - 512]; }
    float qo = q * c + q2 * sn;
    float ko = k * c + k2 * sn;
    int h = j >> 6, d = j & 63;
    int o = ((h * SEQ) + s) * HD + d;
    g_Q[o] = qo;
    g_K[o] = ko;
    g_V[o] = v;
}

// ---------------- TF32 tensor-core GEMM: C = A[M,K]@B[K,N] + bias -------
// 128x128x16 tile, 256 threads = 8 warps (4m x 2n), warp tile 32x64.
// 3xTF32 split (hi*hi + hi*lo + lo*hi) for fp32-grade accuracy.
__device__ __forceinline__
void tf32_gemm_bias_body(int N, int K,
                         const float* __restrict__ A,
                         const float* __restrict__ B,
                         const float* __restrict__ bias,
                         float* __restrict__ C) {
    const int BM = 128, BK = 16;
    __shared__ float As_h[BM][20], As_l[BM][20];      // stride 20 -> frag-conflict-free
    __shared__ float Bs_h[BK][136], Bs_l[BK][136];    // stride 136 -> frag-conflict-free

    int tid = threadIdx.x;
    int w = tid >> 5, lane = tid & 31;
    int g = lane >> 2, c = lane & 3;
    int m0 = blockIdx.y * BM, n0 = blockIdx.x * 128;
    int wm = w >> 1, wn = w & 1;

    float acc[2][8][4];
#pragma unroll
    for (int mi = 0; mi < 2; mi++)
#pragma unroll
        for (int ni = 0; ni < 8; ni++)
#pragma unroll
            for (int i = 0; i < 4; i++) acc[mi][ni][i] = 0.f;

    int am = tid >> 1;            // A loader: row 0..127
    int akq = (tid & 1) * 8;      // k-offset 0 or 8
    int bk = tid >> 4;            // B loader: k-row 0..15
    int bnq = (tid & 15) * 8;     // n-offset 0..120

    for (int k0 = 0; k0 < K; k0 += BK) {
#pragma unroll
        for (int r = 0; r < 2; r++) {
            float4 a4 = *(const float4*)(A + (size_t)(m0 + am) * K + k0 + akq + 4 * r);
            float av[4] = {a4.x, a4.y, a4.z, a4.w};
#pragma unroll
            for (int i = 0; i < 4; i++) {
                float hf = __uint_as_float(f2tf32(av[i]));
                As_h[am][akq + 4 * r + i] = hf;
                As_l[am][akq + 4 * r + i] = av[i] - hf;
            }
            float4 b4 = *(const float4*)(B + (size_t)(k0 + bk) * N + n0 + bnq + 4 * r);
            float bv[4] = {b4.x, b4.y, b4.z, b4.w};
#pragma unroll
            for (int i = 0; i < 4; i++) {
                float hf = __uint_as_float(f2tf32(bv[i]));
                Bs_h[bk][bnq + 4 * r + i] = hf;
                Bs_l[bk][bnq + 4 * r + i] = bv[i] - hf;
            }
        }
        __syncthreads();

#pragma unroll
        for (int kk = 0; kk < 2; kk++) {
            unsigned ah[2][4], al[2][4];
#pragma unroll
            for (int mi = 0; mi < 2; mi++) {
                int rb = wm * 32 + mi * 16;
                ah[mi][0] = __float_as_uint(As_h[rb + g][kk * 8 + c]);
                ah[mi][1] = __float_as_uint(As_h[rb + g + 8][kk * 8 + c]);
                ah[mi][2] = __float_as_uint(As_h[rb + g][kk * 8 + c + 4]);
                ah[mi][3] = __float_as_uint(As_h[rb + g + 8][kk * 8 + c + 4]);
                al[mi][0] = __float_as_uint(As_l[rb + g][kk * 8 + c]);
                al[mi][1] = __float_as_uint(As_l[rb + g + 8][kk * 8 + c]);
                al[mi][2] = __float_as_uint(As_l[rb + g][kk * 8 + c + 4]);
                al[mi][3] = __float_as_uint(As_l[rb + g + 8][kk * 8 + c + 4]);
            }
#pragma unroll
            for (int ni = 0; ni < 8; ni++) {
                int nb = wn * 64 + ni * 8 + g;
                unsigned bh[2], bl[2];
                bh[0] = __float_as_uint(Bs_h[kk * 8 + c][nb]);
                bh[1] = __float_as_uint(Bs_h[kk * 8 + c + 4][nb]);
                bl[0] = __float_as_uint(Bs_l[kk * 8 + c][nb]);
                bl[1] = __float_as_uint(Bs_l[kk * 8 + c + 4][nb]);
#pragma unroll
                for (int mi = 0; mi < 2; mi++) {
                    mma_tf32(acc[mi][ni], ah[mi], bh);
                    mma_tf32(acc[mi][ni], ah[mi], bl);
                    mma_tf32(acc[mi][ni], al[mi], bh);
                }
            }
        }
        __syncthreads();
    }

#pragma unroll
    for (int mi = 0; mi < 2; mi++) {
#pragma unroll
        for (int ni = 0; ni < 8; ni++) {
            int col = n0 + wn * 64 + ni * 8 + 2 * c;
            float2 bb = *(const float2*)(bias + col);
            int row0 = m0 + wm * 32 + mi * 16 + g;
            float2 c0 = make_float2(acc[mi][ni][0] + bb.x, acc[mi][ni][1] + bb.y);
            float2 c1 = make_float2(acc[mi][ni][2] + bb.x, acc[mi][ni][3] + bb.y);
            *(float2*)(C + (size_t)row0 * N + col) = c0;
            *(float2*)(C + (size_t)(row0 + 8) * N + col) = c1;
        }
    }
}

__global__ __launch_bounds__(256, 2)
void tf32_gemm_qkv_kernel(const float* __restrict__ x,
                          const float* __restrict__ Wqkv,
                          const float* __restrict__ bqkv) {
    tf32_gemm_bias_body(3 * DIM, DIM, x, Wqkv, bqkv, g_qkv);
}

__global__ __launch_bounds__(256, 2)
void tf32_gemm_out_kernel(const float* __restrict__ Wo,
                          const float* __restrict__ bo) {
    tf32_gemm_bias_body(DIM, DIM, g_O, Wo, bo, g_att);
}

// ---------------- causal flash attention, TF32 tensor cores -------------
__global__ __launch_bounds__(256, 1)
void flash_mma_kernel() {
    __shared__ float Kh[KT][68], Kl[KT][68];     // [key][dim]
    __shared__ float VTh[64][36], VTl[64][36];   // V^T [dim][key]

    int h = blockIdx.y;
    int m0 = blockIdx.x * 128;
    int tid = threadIdx.x;
    int w = tid >> 5, lane = tid & 31;
    int g = lane >> 2, c = lane & 3;
    int q0w = m0 + w * 16;

    unsigned qh[8][4], ql[8][4];
    {
        const float* Qb = g_Q + ((size_t)h * SEQ + q0w) * HD;
#pragma unroll
        for (int kk = 0; kk < 8; kk++) {
            float v[4];
            v[0] = Qb[(size_t)g * HD + kk * 8 + c] * 0.125f;
            v[1] = Qb[(size_t)(g + 8) * HD + kk * 8 + c] * 0.125f;
            v[2] = Qb[(size_t)g * HD + kk * 8 + c + 4] * 0.125f;
            v[3] = Qb[(size_t)(g + 8) * HD + kk * 8 + c + 4] * 0.125f;
#pragma unroll
            for (int i = 0; i < 4; i++) {
                unsigned hi = f2tf32(v[i]);
                qh[kk][i] = hi;
                ql[kk][i] = __float_as_uint(v[i] - __uint_as_float(hi));
            }
        }
    }

    float o[8][4];
#pragma unroll
    for (int nn = 0; nn < 8; nn++)
#pragma unroll
        for (int i = 0; i < 4; i++) o[nn][i] = 0.f;
    float mrow[2] = {-INFINITY, -INFINITY};
    float lrow[2] = {0.f, 0.f};

    int nT = (m0 + 128) / KT;
    for (int t = 0; t < nT; t++) {
        int kt0 = t * KT;
        __syncthreads();

#pragma unroll
        for (int r = 0; r < 2; r++) {
            int f4 = tid * 2 + r;
            int key = f4 >> 4;
            int d = (f4 & 15) * 4;
            const float* Kg = g_K + ((size_t)h * SEQ + kt0 + key) * HD + d;
            const float* Vg = g_V + ((size_t)h * SEQ + kt0 + key) * HD + d;
            float4 kv = *(const float4*)Kg;
            float4 vv = *(const float4*)Vg;
            float kt[4] = {kv.x, kv.y, kv.z, kv.w};
            float vt[4] = {vv.x, vv.y, vv.z, vv.w};
            float khv[4], klv[4];
#pragma unroll
            for (int i = 0; i < 4; i++) {
                float hf = __uint_as_float(f2tf32(kt[i]));
                khv[i] = hf;
                klv[i] = kt[i] - hf;
            }
            *(float4*)&Kh[key][d] = make_float4(khv[0], khv[1], khv[2], khv[3]);
            *(float4*)&Kl[key][d] = make_float4(klv[0], klv[1], klv[2], klv[3]);
#pragma unroll
            for (int i = 0; i < 4; i++) {
                float hf = __uint_as_float(f2tf32(vt[i]));
                VTh[d + i][key] = hf;
                VTl[d + i][key] = vt[i] - hf;
            }
        }
        __syncthreads();

        if (kt0 <= q0w + 15) {
            float s[4][4];
#pragma unroll
            for (int nn = 0; nn < 4; nn++)
#pragma unroll
                for (int i = 0; i < 4; i++) s[nn][i] = 0.f;
#pragma unroll
            for (int kk = 0; kk < 8; kk++) {
#pragma unroll
                for (int nn = 0; nn < 4; nn++) {
                    unsigned bh[2], bl[2];
                    bh[0] = __float_as_uint(Kh[nn * 8 + g][kk * 8 + c]);
                    bh[1] = __float_as_uint(Kh[nn * 8 + g][kk * 8 + c + 4]);
                    bl[0] = __float_as_uint(Kl[nn * 8 + g][kk * 8 + c]);
                    bl[1] = __float_as_uint(Kl[nn * 8 + g][kk * 8 + c + 4]);
                    mma_tf32(s[nn], qh[kk], bh);
                    mma_tf32(s[nn], qh[kk], bl);
                    mma_tf32(s[nn], ql[kk], bh);
                }
            }

            float tmax[2] = {-INFINITY, -INFINITY};
#pragma unroll
            for (int nn = 0; nn < 4; nn++) {
#pragma unroll
                for (int i = 0; i < 4; i++) {
                    int qrow = q0w + g + ((i >> 1) << 3);
                    int kcol = kt0 + nn * 8 + 2 * c + (i & 1);
                    if (kcol > qrow) s[nn][i] = -INFINITY;
                    tmax[i >> 1] = fmaxf(tmax[i >> 1], s[nn][i]);
                }
            }
#pragma unroll
            for (int off = 1; off <= 2; off <<= 1) {
                tmax[0] = fmaxf(tmax[0], __shfl_xor_sync(0xffffffffu, tmax[0], off));
                tmax[1] = fmaxf(tmax[1], __shfl_xor_sync(0xffffffffu, tmax[1], off));
            }
            float mnew0 = fmaxf(mrow[0], tmax[0]);
            float mnew1 = fmaxf(mrow[1], tmax[1]);
            float corr0 = __expf(mrow[0] - mnew0);
            float corr1 = __expf(mrow[1] - mnew1);
            mrow[0] = mnew0; mrow[1] = mnew1;

            float rsum[2] = {0.f, 0.f};
#pragma unroll
            for (int nn = 0; nn < 4; nn++) {
#pragma unroll
                for (int i = 0; i < 4; i++) {
                    float p = __expf(s[nn][i] - ((i >> 1) ? mnew1 : mnew0));
                    s[nn][i] = p;
                    rsum[i >> 1] += p;
                }
            }
#pragma unroll
            for (int off = 1; off <= 2; off <<= 1) {
                rsum[0] += __shfl_xor_sync(0xffffffffu, rsum[0], off);
                rsum[1] += __shfl_xor_sync(0xffffffffu, rsum[1], off);
            }
            lrow[0] = lrow[0] * corr0 + rsum[0];
            lrow[1] = lrow[1] * corr1 + rsum[1];
#pragma unroll
            for (int nn = 0; nn < 8; nn++) {
                o[nn][0] *= corr0; o[nn][1] *= corr0;
                o[nn][2] *= corr1; o[nn][3] *= corr1;
            }

            int src0 = (lane & ~3) | (c >> 1);
            int src2 = src0 + 2;
#pragma unroll
            for (int kk = 0; kk < 4; kk++) {
                float x0 = __shfl_sync(0xffffffffu, s[kk][0], src0);
                float x1 = __shfl_sync(0xffffffffu, s[kk][1], src0);
                float y0 = __shfl_sync(0xffffffffu, s[kk][2], src0);
                float y1 = __shfl_sync(0xffffffffu, s[kk][3], src0);
                float z0 = __shfl_sync(0xffffffffu, s[kk][0], src2);
                float z1 = __shfl_sync(0xffffffffu, s[kk][1], src2);
                float u0 = __shfl_sync(0xffffffffu, s[kk][2], src2);
                float u1 = __shfl_sync(0xffffffffu, s[kk][3], src2);
                float af[4];
                af[0] = (c & 1) ? x1 : x0;
                af[1] = (c & 1) ? y1 : y0;
                af[2] = (c & 1) ? z1 : z0;
                af[3] = (c & 1) ? u1 : u0;
                unsigned ah[4], al[4];
#pragma unroll
                for (int i = 0; i < 4; i++) {
                    unsigned hi = f2tf32(af[i]);
                    ah[i] = hi;
                    al[i] = __float_as_uint(af[i] - __uint_as_float(hi));
                }
#pragma unroll
                for (int nn = 0; nn < 8; nn++) {
                    unsigned bh[2], bl[2];
                    bh[0] = __float_as_uint(VTh[nn * 8 + g][kk * 8 + c]);
                    bh[1] = __float_as_uint(VTh[nn * 8 + g][kk * 8 + c + 4]);
                    bl[0] = __float_as_uint(VTl[nn * 8 + g][kk * 8 + c]);
                    bl[1] = __float_as_uint(VTl[nn * 8 + g][kk * 8 + c + 4]);
                    mma_tf32(o[nn], ah, bh);
                    mma_tf32(o[nn], ah, bl);
                    mma_tf32(o[nn], al, bh);
                }
            }
        }
    }

    float inv0 = 1.f / lrow[0];
    float inv1 = 1.f / lrow[1];
#pragma unroll
    for (int nn = 0; nn < 8; nn++) {
        int d = h * HD + nn * 8 + 2 * c;
        float2 r0 = make_float2(o[nn][0] * inv0, o[nn][1] * inv0);
        float2 r1 = make_float2(o[nn][2] * inv1, o[nn][3] * inv1);
        *(float2*)(g_O + (size_t)(q0w + g) * DIM + d) = r0;
        *(float2*)(g_O + (size_t)(q0w + g + 8) * DIM + d) = r1;
    }
}

// ---------------- LayerNorm over last dim (1024) ------------------------
__global__ __launch_bounds__(256)
void layernorm_kernel(const float* __restrict__ gamma,
                      const float* __restrict__ beta,
                      float* __restrict__ Y) {
    int r = blockIdx.x;
    const float* x = g_att + (size_t)r * DIM;
    int tid = threadIdx.x;

    float s = 0.f, s2 = 0.f;
#pragma unroll
    for (int it = 0; it < DIM / 256; it++) {
        float v = x[tid + it * 256];
        s += v;
        s2 += v * v;
    }
#pragma unroll
    for (int off = 16; off; off >>= 1) {
        s  += __shfl_xor_sync(0xffffffffu, s, off);
        s2 += __shfl_xor_sync(0xffffffffu, s2, off);
    }
    __shared__ float ws[8], ws2[8];
    int w = tid >> 5, lane = tid & 31;
    if (lane == 0) { ws[w] = s; ws2[w] = s2; }
    __syncthreads();
    float S1 = 0.f, S2 = 0.f;
#pragma unroll
    for (int i = 0; i < 8; i++) { S1 += ws[i]; S2 += ws2[i]; }

    float mu  = S1 * (1.f / DIM);
    float var = S2 * (1.f / DIM) - mu * mu;
    float inv = rsqrtf(var + 1e-5f);
#pragma unroll
    for (int it = 0; it < DIM / 256; it++) {
        int j = tid + it * 256;
        float v = x[j];
        Y[(size_t)r * DIM + j] = (v - mu) * inv * gamma[j] + beta[j];
    }
}

// ---------------- launch (pure kernel launches, no runtime API) ---------
extern "C" void kernel_launch(void* const* d_in, const int* in_sizes, int n_in,
                              void* d_out, int out_size) {
    const float* x     = (const float*)d_in[0];
    const float* Wqkv  = (const float*)d_in[1];
    const float* bqkv  = (const float*)d_in[2];
    const float* Wo    = (const float*)d_in[3];
    const float* bo    = (const float*)d_in[4];
    const float* gamma = (const float*)d_in[5];
    const float* beta  = (const float*)d_in[6];
    float* out = (float*)d_out;

    rope_tables_kernel<<<(SEQ * 512) / 256, 256>>>();
    tf32_gemm_qkv_kernel<<<dim3(3 * DIM / 128, SEQ / 128), 256>>>(x, Wqkv, bqkv);
    rope_scatter_kernel<<<(SEQ * DIM) / 256, 256>>>();
    flash_mma_kernel<<<dim3(SEQ / 128, NH), 256>>>();
    tf32_gemm_out_kernel<<<dim3(DIM / 128, SEQ / 128), 256>>>(Wo, bo);
    layernorm_kernel<<<SEQ, 256>>>(gamma, beta, out);
}

// round 7
// speedup vs baseline: 1.3990x; 1.3990x over previous
#include <cuda_runtime.h>
#include <cuda_bf16.h>
#include <math.h>

#define SEQ 4096
#define DIM 1024
#define NH  16
#define HD  64
#define KT  32   // keys per flash tile

// ---------------- device scratch (no allocation allowed) ----------------
__device__ float g_qkv[SEQ * 3 * DIM];     // QKV projection output
__device__ float g_Q[NH * SEQ * HD];       // roped, head-major
__device__ float g_K[NH * SEQ * HD];
__device__ float g_V[NH * SEQ * HD];
__device__ float g_O[SEQ * DIM];           // attention output (s, dim)
__device__ float g_att[SEQ * DIM];         // after out-proj, pre-LN
__device__ float g_cos[SEQ * 512];
__device__ float g_sin[SEQ * 512];
__device__ float g_invf[512];

// ---------------- TF32 helpers (flash kernel, unchanged) ----------------
__device__ __forceinline__ unsigned f2tf32(float x) {
    unsigned r;
    asm("cvt.rna.tf32.f32 %0, %1;" : "=r"(r) : "f"(x));
    return r;
}
__device__ __forceinline__ void mma_tf32(float* c, const unsigned* a, const unsigned* b) {
    asm volatile(
        "mma.sync.aligned.m16n8k8.row.col.f32.tf32.tf32.f32 "
        "{%0,%1,%2,%3}, {%4,%5,%6,%7}, {%8,%9}, {%0,%1,%2,%3};"
        : "+f"(c[0]), "+f"(c[1]), "+f"(c[2]), "+f"(c[3])
        : "r"(a[0]), "r"(a[1]), "r"(a[2]), "r"(a[3]), "r"(b[0]), "r"(b[1]));
}

// ---------------- BF16 helpers (GEMMs) ----------------------------------
__device__ __forceinline__ void mma_bf16(float* c, const unsigned* a, const unsigned* b) {
    asm volatile(
        "mma.sync.aligned.m16n8k16.row.col.f32.bf16.bf16.f32 "
        "{%0,%1,%2,%3}, {%4,%5,%6,%7}, {%8,%9}, {%0,%1,%2,%3};"
        : "+f"(c[0]), "+f"(c[1]), "+f"(c[2]), "+f"(c[3])
        : "r"(a[0]), "r"(a[1]), "r"(a[2]), "r"(a[3]), "r"(b[0]), "r"(b[1]));
}
// split a,b (consecutive along k) into hi/lo bf16, pack k-pairs into regs
__device__ __forceinline__ void split_pack(float a, float b, unsigned& h, unsigned& l) {
    __nv_bfloat16 ah = __float2bfloat16_rn(a);
    __nv_bfloat16 bh = __float2bfloat16_rn(b);
    float ar = a - __bfloat162float(ah);
    float br = b - __bfloat162float(bh);
    __nv_bfloat162 hv; hv.x = ah; hv.y = bh;
    __nv_bfloat162 lv = __floats2bfloat162_rn(ar, br);
    h = *reinterpret_cast<unsigned*>(&hv);
    l = *reinterpret_cast<unsigned*>(&lv);
}

// ---------------- RoPE tables -------------------------------------------
// inv_freq once in double (512 values, trivial cost)
__global__ void rope_invf_kernel() {
    int i = blockIdx.x * blockDim.x + threadIdx.x;
    if (i < 512)
        g_invf[i] = (float)exp(-((double)i) * (9.210340371976184 / 512.0));
}
// angle = fp32(s * invf) exactly like the fp32 reference; range-reduce that
// angle in double (exact), then cheap fp32 trig on |r| <= pi.
__global__ void rope_tables_kernel() {
    int idx = blockIdx.x * blockDim.x + threadIdx.x;
    if (idx >= SEQ * 512) return;
    int s = idx >> 9;
    int i = idx & 511;
    float ang = (float)s * g_invf[i];
    double a = (double)ang;
    double k = rint(a * 0.15915494309189535);
    float r = (float)(a - k * 6.283185307179586);
    g_cos[idx] = cosf(r);
    g_sin[idx] = sinf(r);
}

// ---------------- RoPE apply + scatter to head-major Q/K/V --------------
__global__ void rope_scatter_kernel() {
    int idx = blockIdx.x * blockDim.x + threadIdx.x;   // SEQ*DIM threads
    int s = idx >> 10;
    int j = idx & 1023;
    int i = j & 511;
    float c  = g_cos[(s << 9) + i];
    float sn = g_sin[(s << 9) + i];
    const float* row = g_qkv + (size_t)s * (3 * DIM);
    float q = row[j];
    float k = row[DIM + j];
    float v = row[2 * DIM + j];
    float q2, k2;
    if (j < 512) { q2 = -row[j + 512];       k2 = -row[DIM + j + 512]; }
    else         { q2 =  row[j - 512];       k2 =  row[DIM + j - 512]; }
    float qo = q * c + q2 * sn;
    float ko = k * c + k2 * sn;
    int h = j >> 6, d = j & 63;
    int o = ((h * SEQ) + s) * HD + d;
    g_Q[o] = qo;
    g_K[o] = ko;
    g_V[o] = v;
}

// ---------------- BF16x3 tensor-core GEMM: C = A@B + bias ---------------
// 128x128x32 tile, 256 threads = 8 warps (4m x 2n), warp tile 32x64.
// mma.m16n8k16.bf16, 3-product split (hh + hl + lh), packed k-pairs in smem.
__device__ __forceinline__
void bf16_gemm_bias_body(int N, int K,
                         const float* __restrict__ A,
                         const float* __restrict__ B,
                         const float* __restrict__ bias,
                         float* __restrict__ C) {
    __shared__ unsigned As_h[128][20], As_l[128][20];   // [m][kpair], stride 20 -> conflict-free
    __shared__ unsigned Bs_h[16][136], Bs_l[16][136];   // [kpair][n], stride 136 -> conflict-free

    int tid = threadIdx.x;
    int w = tid >> 5, lane = tid & 31;
    int g = lane >> 2, c = lane & 3;
    int m0 = blockIdx.y * 128, n0 = blockIdx.x * 128;
    int wm = w >> 1, wn = w & 1;

    float acc[2][8][4];
#pragma unroll
    for (int mi = 0; mi < 2; mi++)
#pragma unroll
        for (int ni = 0; ni < 8; ni++)
#pragma unroll
            for (int i = 0; i < 4; i++) acc[mi][ni][i] = 0.f;

    int am = tid >> 1, ak0 = (tid & 1) * 16;   // A loader: row, k-offset
    int bkp = tid >> 4, bn8 = (tid & 15) * 8;  // B loader: k-pair, n-offset

    for (int k0 = 0; k0 < K; k0 += 32) {
        const float* Ap = A + (size_t)(m0 + am) * K + k0 + ak0;
#pragma unroll
        for (int q = 0; q < 4; q++) {
            float4 a4 = *(const float4*)(Ap + 4 * q);
            unsigned h0, l0, h1, l1;
            split_pack(a4.x, a4.y, h0, l0);
            split_pack(a4.z, a4.w, h1, l1);
            int kp = (ak0 >> 1) + 2 * q;
            As_h[am][kp] = h0;     As_l[am][kp] = l0;
            As_h[am][kp + 1] = h1; As_l[am][kp + 1] = l1;
        }
        const float* Bp0 = B + (size_t)(k0 + 2 * bkp) * N + n0 + bn8;
        const float* Bp1 = Bp0 + N;
#pragma unroll
        for (int q = 0; q < 2; q++) {
            float4 b0 = *(const float4*)(Bp0 + 4 * q);
            float4 b1 = *(const float4*)(Bp1 + 4 * q);
            unsigned h, l;
            split_pack(b0.x, b1.x, h, l); Bs_h[bkp][bn8 + 4 * q + 0] = h; Bs_l[bkp][bn8 + 4 * q + 0] = l;
            split_pack(b0.y, b1.y, h, l); Bs_h[bkp][bn8 + 4 * q + 1] = h; Bs_l[bkp][bn8 + 4 * q + 1] = l;
            split_pack(b0.z, b1.z, h, l); Bs_h[bkp][bn8 + 4 * q + 2] = h; Bs_l[bkp][bn8 + 4 * q + 2] = l;
            split_pack(b0.w, b1.w, h, l); Bs_h[bkp][bn8 + 4 * q + 3] = h; Bs_l[bkp][bn8 + 4 * q + 3] = l;
        }
        __syncthreads();

#pragma unroll
        for (int kk = 0; kk < 2; kk++) {
            unsigned ah[2][4], al[2][4];
#pragma unroll
            for (int mi = 0; mi < 2; mi++) {
                int rb = wm * 32 + mi * 16;
                ah[mi][0] = As_h[rb + g][kk * 8 + c];
                ah[mi][1] = As_h[rb + g + 8][kk * 8 + c];
                ah[mi][2] = As_h[rb + g][kk * 8 + c + 4];
                ah[mi][3] = As_h[rb + g + 8][kk * 8 + c + 4];
                al[mi][0] = As_l[rb + g][kk * 8 + c];
                al[mi][1] = As_l[rb + g + 8][kk * 8 + c];
                al[mi][2] = As_l[rb + g][kk * 8 + c + 4];
                al[mi][3] = As_l[rb + g + 8][kk * 8 + c + 4];
            }
#pragma unroll
            for (int ni = 0; ni < 8; ni++) {
                int nb = wn * 64 + ni * 8 + g;
                unsigned bh[2], bl[2];
                bh[0] = Bs_h[kk * 8 + c][nb];
                bh[1] = Bs_h[kk * 8 + c + 4][nb];
                bl[0] = Bs_l[kk * 8 + c][nb];
                bl[1] = Bs_l[kk * 8 + c + 4][nb];
#pragma unroll
                for (int mi = 0; mi < 2; mi++) {
                    mma_bf16(acc[mi][ni], ah[mi], bh);
                    mma_bf16(acc[mi][ni], ah[mi], bl);
                    mma_bf16(acc[mi][ni], al[mi], bh);
                }
            }
        }
        __syncthreads();
    }

#pragma unroll
    for (int mi = 0; mi < 2; mi++) {
#pragma unroll
        for (int ni = 0; ni < 8; ni++) {
            int col = n0 + wn * 64 + ni * 8 + 2 * c;
            float2 bb = *(const float2*)(bias + col);
            int row0 = m0 + wm * 32 + mi * 16 + g;
            float2 c0 = make_float2(acc[mi][ni][0] + bb.x, acc[mi][ni][1] + bb.y);
            float2 c1 = make_float2(acc[mi][ni][2] + bb.x, acc[mi][ni][3] + bb.y);
            *(float2*)(C + (size_t)row0 * N + col) = c0;
            *(float2*)(C + (size_t)(row0 + 8) * N + col) = c1;
        }
    }
}

__global__ __launch_bounds__(256, 2)
void bf16_gemm_qkv_kernel(const float* __restrict__ x,
                          const float* __restrict__ Wqkv,
                          const float* __restrict__ bqkv) {
    bf16_gemm_bias_body(3 * DIM, DIM, x, Wqkv, bqkv, g_qkv);
}

__global__ __launch_bounds__(256, 2)
void bf16_gemm_out_kernel(const float* __restrict__ Wo,
                          const float* __restrict__ bo) {
    bf16_gemm_bias_body(DIM, DIM, g_O, Wo, bo, g_att);
}

// ---------------- causal flash attention, TF32 tensor cores (unchanged) -
__global__ __launch_bounds__(256, 1)
void flash_mma_kernel() {
    __shared__ float Kh[KT][68], Kl[KT][68];     // [key][dim]
    __shared__ float VTh[64][36], VTl[64][36];   // V^T [dim][key]

    int h = blockIdx.y;
    int m0 = blockIdx.x * 128;
    int tid = threadIdx.x;
    int w = tid >> 5, lane = tid & 31;
    int g = lane >> 2, c = lane & 3;
    int q0w = m0 + w * 16;

    unsigned qh[8][4], ql[8][4];
    {
        const float* Qb = g_Q + ((size_t)h * SEQ + q0w) * HD;
#pragma unroll
        for (int kk = 0; kk < 8; kk++) {
            float v[4];
            v[0] = Qb[(size_t)g * HD + kk * 8 + c] * 0.125f;
            v[1] = Qb[(size_t)(g + 8) * HD + kk * 8 + c] * 0.125f;
            v[2] = Qb[(size_t)g * HD + kk * 8 + c + 4] * 0.125f;
            v[3] = Qb[(size_t)(g + 8) * HD + kk * 8 + c + 4] * 0.125f;
#pragma unroll
            for (int i = 0; i < 4; i++) {
                unsigned hi = f2tf32(v[i]);
                qh[kk][i] = hi;
                ql[kk][i] = __float_as_uint(v[i] - __uint_as_float(hi));
            }
        }
    }

    float o[8][4];
#pragma unroll
    for (int nn = 0; nn < 8; nn++)
#pragma unroll
        for (int i = 0; i < 4; i++) o[nn][i] = 0.f;
    float mrow[2] = {-INFINITY, -INFINITY};
    float lrow[2] = {0.f, 0.f};

    int nT = (m0 + 128) / KT;
    for (int t = 0; t < nT; t++) {
        int kt0 = t * KT;
        __syncthreads();

#pragma unroll
        for (int r = 0; r < 2; r++) {
            int f4 = tid * 2 + r;
            int key = f4 >> 4;
            int d = (f4 & 15) * 4;
            const float* Kg = g_K + ((size_t)h * SEQ + kt0 + key) * HD + d;
            const float* Vg = g_V + ((size_t)h * SEQ + kt0 + key) * HD + d;
            float4 kv = *(const float4*)Kg;
            float4 vv = *(const float4*)Vg;
            float kt[4] = {kv.x, kv.y, kv.z, kv.w};
            float vt[4] = {vv.x, vv.y, vv.z, vv.w};
            float khv[4], klv[4];
#pragma unroll
            for (int i = 0; i < 4; i++) {
                float hf = __uint_as_float(f2tf32(kt[i]));
                khv[i] = hf;
                klv[i] = kt[i] - hf;
            }
            *(float4*)&Kh[key][d] = make_float4(khv[0], khv[1], khv[2], khv[3]);
            *(float4*)&Kl[key][d] = make_float4(klv[0], klv[1], klv[2], klv[3]);
#pragma unroll
            for (int i = 0; i < 4; i++) {
                float hf = __uint_as_float(f2tf32(vt[i]));
                VTh[d + i][key] = hf;
                VTl[d + i][key] = vt[i] - hf;
            }
        }
        __syncthreads();

        if (kt0 <= q0w + 15) {
            float s[4][4];
#pragma unroll
            for (int nn = 0; nn < 4; nn++)
#pragma unroll
                for (int i = 0; i < 4; i++) s[nn][i] = 0.f;
#pragma unroll
            for (int kk = 0; kk < 8; kk++) {
#pragma unroll
                for (int nn = 0; nn < 4; nn++) {
                    unsigned bh[2], bl[2];
                    bh[0] = __float_as_uint(Kh[nn * 8 + g][kk * 8 + c]);
                    bh[1] = __float_as_uint(Kh[nn * 8 + g][kk * 8 + c + 4]);
                    bl[0] = __float_as_uint(Kl[nn * 8 + g][kk * 8 + c]);
                    bl[1] = __float_as_uint(Kl[nn * 8 + g][kk * 8 + c + 4]);
                    mma_tf32(s[nn], qh[kk], bh);
                    mma_tf32(s[nn], qh[kk], bl);
                    mma_tf32(s[nn], ql[kk], bh);
                }
            }

            float tmax[2] = {-INFINITY, -INFINITY};
#pragma unroll
            for (int nn = 0; nn < 4; nn++) {
#pragma unroll
                for (int i = 0; i < 4; i++) {
                    int qrow = q0w + g + ((i >> 1) << 3);
                    int kcol = kt0 + nn * 8 + 2 * c + (i & 1);
                    if (kcol > qrow) s[nn][i] = -INFINITY;
                    tmax[i >> 1] = fmaxf(tmax[i >> 1], s[nn][i]);
                }
            }
#pragma unroll
            for (int off = 1; off <= 2; off <<= 1) {
                tmax[0] = fmaxf(tmax[0], __shfl_xor_sync(0xffffffffu, tmax[0], off));
                tmax[1] = fmaxf(tmax[1], __shfl_xor_sync(0xffffffffu, tmax[1], off));
            }
            float mnew0 = fmaxf(mrow[0], tmax[0]);
            float mnew1 = fmaxf(mrow[1], tmax[1]);
            float corr0 = __expf(mrow[0] - mnew0);
            float corr1 = __expf(mrow[1] - mnew1);
            mrow[0] = mnew0; mrow[1] = mnew1;

            float rsum[2] = {0.f, 0.f};
#pragma unroll
            for (int nn = 0; nn < 4; nn++) {
#pragma unroll
                for (int i = 0; i < 4; i++) {
                    float p = __expf(s[nn][i] - ((i >> 1) ? mnew1 : mnew0));
                    s[nn][i] = p;
                    rsum[i >> 1] += p;
                }
            }
#pragma unroll
            for (int off = 1; off <= 2; off <<= 1) {
                rsum[0] += __shfl_xor_sync(0xffffffffu, rsum[0], off);
                rsum[1] += __shfl_xor_sync(0xffffffffu, rsum[1], off);
            }
            lrow[0] = lrow[0] * corr0 + rsum[0];
            lrow[1] = lrow[1] * corr1 + rsum[1];
#pragma unroll
            for (int nn = 0; nn < 8; nn++) {
                o[nn][0] *= corr0; o[nn][1] *= corr0;
                o[nn][2] *= corr1; o[nn][3] *= corr1;
            }

            int src0 = (lane & ~3) | (c >> 1);
            int src2 = src0 + 2;
#pragma unroll
            for (int kk = 0; kk < 4; kk++) {
                float x0 = __shfl_sync(0xffffffffu, s[kk][0], src0);
                float x1 = __shfl_sync(0xffffffffu, s[kk][1], src0);
                float y0 = __shfl_sync(0xffffffffu, s[kk][2], src0);
                float y1 = __shfl_sync(0xffffffffu, s[kk][3], src0);
                float z0 = __shfl_sync(0xffffffffu, s[kk][0], src2);
                float z1 = __shfl_sync(0xffffffffu, s[kk][1], src2);
                float u0 = __shfl_sync(0xffffffffu, s[kk][2], src2);
                float u1 = __shfl_sync(0xffffffffu, s[kk][3], src2);
                float af[4];
                af[0] = (c & 1) ? x1 : x0;
                af[1] = (c & 1) ? y1 : y0;
                af[2] = (c & 1) ? z1 : z0;
                af[3] = (c & 1) ? u1 : u0;
                unsigned ah[4], al[4];
#pragma unroll
                for (int i = 0; i < 4; i++) {
                    unsigned hi = f2tf32(af[i]);
                    ah[i] = hi;
                    al[i] = __float_as_uint(af[i] - __uint_as_float(hi));
                }
#pragma unroll
                for (int nn = 0; nn < 8; nn++) {
                    unsigned bh[2], bl[2];
                    bh[0] = __float_as_uint(VTh[nn * 8 + g][kk * 8 + c]);
                    bh[1] = __float_as_uint(VTh[nn * 8 + g][kk * 8 + c + 4]);
                    bl[0] = __float_as_uint(VTl[nn * 8 + g][kk * 8 + c]);
                    bl[1] = __float_as_uint(VTl[nn * 8 + g][kk * 8 + c + 4]);
                    mma_tf32(o[nn], ah, bh);
                    mma_tf32(o[nn], ah, bl);
                    mma_tf32(o[nn], al, bh);
                }
            }
        }
    }

    float inv0 = 1.f / lrow[0];
    float inv1 = 1.f / lrow[1];
#pragma unroll
    for (int nn = 0; nn < 8; nn++) {
        int d = h * HD + nn * 8 + 2 * c;
        float2 r0 = make_float2(o[nn][0] * inv0, o[nn][1] * inv0);
        float2 r1 = make_float2(o[nn][2] * inv1, o[nn][3] * inv1);
        *(float2*)(g_O + (size_t)(q0w + g) * DIM + d) = r0;
        *(float2*)(g_O + (size_t)(q0w + g + 8) * DIM + d) = r1;
    }
}

// ---------------- LayerNorm over last dim (1024) ------------------------
__global__ __launch_bounds__(256)
void layernorm_kernel(const float* __restrict__ gamma,
                      const float* __restrict__ beta,
                      float* __restrict__ Y) {
    int r = blockIdx.x;
    const float* x = g_att + (size_t)r * DIM;
    int tid = threadIdx.x;

    float s = 0.f, s2 = 0.f;
#pragma unroll
    for (int it = 0; it < DIM / 256; it++) {
        float v = x[tid + it * 256];
        s += v;
        s2 += v * v;
    }
#pragma unroll
    for (int off = 16; off; off >>= 1) {
        s  += __shfl_xor_sync(0xffffffffu, s, off);
        s2 += __shfl_xor_sync(0xffffffffu, s2, off);
    }
    __shared__ float ws[8], ws2[8];
    int w = tid >> 5, lane = tid & 31;
    if (lane == 0) { ws[w] = s; ws2[w] = s2; }
    __syncthreads();
    float S1 = 0.f, S2 = 0.f;
#pragma unroll
    for (int i = 0; i < 8; i++) { S1 += ws[i]; S2 += ws2[i]; }

    float mu  = S1 * (1.f / DIM);
    float var = S2 * (1.f / DIM) - mu * mu;
    float inv = rsqrtf(var + 1e-5f);
#pragma unroll
    for (int it = 0; it < DIM / 256; it++) {
        int j = tid + it * 256;
        float v = x[j];
        Y[(size_t)r * DIM + j] = (v - mu) * inv * gamma[j] + beta[j];
    }
}

// ---------------- launch (pure kernel launches, no runtime API) ---------
extern "C" void kernel_launch(void* const* d_in, const int* in_sizes, int n_in,
                              void* d_out, int out_size) {
    const float* x     = (const float*)d_in[0];
    const float* Wqkv  = (const float*)d_in[1];
    const float* bqkv  = (const float*)d_in[2];
    const float* Wo    = (const float*)d_in[3];
    const float* bo    = (const float*)d_in[4];
    const float* gamma = (const float*)d_in[5];
    const float* beta  = (const float*)d_in[6];
    float* out = (float*)d_out;

    rope_invf_kernel<<<2, 256>>>();
    rope_tables_kernel<<<(SEQ * 512) / 256, 256>>>();
    bf16_gemm_qkv_kernel<<<dim3(3 * DIM / 128, SEQ / 128), 256>>>(x, Wqkv, bqkv);
    rope_scatter_kernel<<<(SEQ * DIM) / 256, 256>>>();
    flash_mma_kernel<<<dim3(SEQ / 128, NH), 256>>>();
    bf16_gemm_out_kernel<<<dim3(DIM / 128, SEQ / 128), 256>>>(Wo, bo);
    layernorm_kernel<<<SEQ, 256>>>(gamma, beta, out);
}

// round 9
// speedup vs baseline: 1.9211x; 1.3731x over previous
#include <cuda_runtime.h>
#include <cuda_bf16.h>
#include <math.h>

#define SEQ 4096
#define DIM 1024
#define NH  16
#define HD  64
#define KT  32   // keys per flash tile

// ---------------- device scratch (no allocation allowed) ----------------
__device__ float g_qkv[SEQ * 3 * DIM];     // QKV projection output
__device__ float g_Q[NH * SEQ * HD];       // roped, head-major
__device__ float g_K[NH * SEQ * HD];
__device__ float g_V[NH * SEQ * HD];
__device__ float g_O[SEQ * DIM];           // attention output (s, dim)
__device__ float g_att[SEQ * DIM];         // after out-proj, pre-LN
__device__ float g_cos[SEQ * 512];
__device__ float g_sin[SEQ * 512];
__device__ float g_invf[512];

// ---------------- BF16 helpers ------------------------------------------
__device__ __forceinline__ void mma_bf16(float* c, const unsigned* a, const unsigned* b) {
    asm volatile(
        "mma.sync.aligned.m16n8k16.row.col.f32.bf16.bf16.f32 "
        "{%0,%1,%2,%3}, {%4,%5,%6,%7}, {%8,%9}, {%0,%1,%2,%3};"
        : "+f"(c[0]), "+f"(c[1]), "+f"(c[2]), "+f"(c[3])
        : "r"(a[0]), "r"(a[1]), "r"(a[2]), "r"(a[3]), "r"(b[0]), "r"(b[1]));
}
// split a,b (consecutive along k) into hi/lo bf16 packed pairs
__device__ __forceinline__ void split_pack(float a, float b, unsigned& h, unsigned& l) {
    __nv_bfloat16 ah = __float2bfloat16_rn(a);
    __nv_bfloat16 bh = __float2bfloat16_rn(b);
    float ar = a - __bfloat162float(ah);
    float br = b - __bfloat162float(bh);
    __nv_bfloat162 hv; hv.x = ah; hv.y = bh;
    __nv_bfloat162 lv = __floats2bfloat162_rn(ar, br);
    h = *reinterpret_cast<unsigned*>(&hv);
    l = *reinterpret_cast<unsigned*>(&lv);
}
__device__ __forceinline__ void ldsm_x4_trans(unsigned& r0, unsigned& r1,
                                              unsigned& r2, unsigned& r3, unsigned addr) {
    asm volatile("ldmatrix.sync.aligned.m8n8.x4.trans.shared.b16 {%0,%1,%2,%3}, [%4];"
                 : "=r"(r0), "=r"(r1), "=r"(r2), "=r"(r3) : "r"(addr));
}

// ---------------- RoPE tables -------------------------------------------
__global__ void rope_invf_kernel() {
    int i = blockIdx.x * blockDim.x + threadIdx.x;
    if (i < 512)
        g_invf[i] = (float)exp(-((double)i) * (9.210340371976184 / 512.0));
}
__global__ void rope_tables_kernel() {
    int idx = blockIdx.x * blockDim.x + threadIdx.x;
    if (idx >= SEQ * 512) return;
    int s = idx >> 9;
    int i = idx & 511;
    float ang = (float)s * g_invf[i];
    double a = (double)ang;
    double k = rint(a * 0.15915494309189535);
    float r = (float)(a - k * 6.283185307179586);
    g_cos[idx] = cosf(r);
    g_sin[idx] = sinf(r);
}

// ---------------- RoPE apply + scatter to head-major Q/K/V --------------
__global__ void rope_scatter_kernel() {
    int idx = blockIdx.x * blockDim.x + threadIdx.x;   // SEQ*DIM threads
    int s = idx >> 10;
    int j = idx & 1023;
    int i = j & 511;
    float c  = g_cos[(s << 9) + i];
    float sn = g_sin[(s << 9) + i];
    const float* row = g_qkv + (size_t)s * (3 * DIM);
    float q = row[j];
    float k = row[DIM + j];
    float v = row[2 * DIM + j];
    float q2, k2;
    if (j < 512) { q2 = -row[j + 512];       k2 = -row[DIM + j + 512]; }
    else         { q2 =  row[j - 512];       k2 =  row[DIM + j - 512]; }
    float qo = q * c + q2 * sn;
    float ko = k * c + k2 * sn;
    int h = j >> 6, d = j & 63;
    int o = ((h * SEQ) + s) * HD + d;
    g_Q[o] = qo;
    g_K[o] = ko;
    g_V[o] = v;
}

// ---------------- BF16x3 tensor-core GEMM: C = A@B + bias ---------------
__device__ __forceinline__
void bf16_gemm_bias_body(int N, int K,
                         const float* __restrict__ A,
                         const float* __restrict__ B,
                         const float* __restrict__ bias,
                         float* __restrict__ C) {
    __shared__ unsigned As_h[128][20], As_l[128][20];
    __shared__ unsigned Bs_h[16][136], Bs_l[16][136];

    int tid = threadIdx.x;
    int w = tid >> 5, lane = tid & 31;
    int g = lane >> 2, c = lane & 3;
    int m0 = blockIdx.y * 128, n0 = blockIdx.x * 128;
    int wm = w >> 1, wn = w & 1;

    float acc[2][8][4];
#pragma unroll
    for (int mi = 0; mi < 2; mi++)
#pragma unroll
        for (int ni = 0; ni < 8; ni++)
#pragma unroll
            for (int i = 0; i < 4; i++) acc[mi][ni][i] = 0.f;

    int am = tid >> 1, ak0 = (tid & 1) * 16;
    int bkp = tid >> 4, bn8 = (tid & 15) * 8;

    for (int k0 = 0; k0 < K; k0 += 32) {
        const float* Ap = A + (size_t)(m0 + am) * K + k0 + ak0;
#pragma unroll
        for (int q = 0; q < 4; q++) {
            float4 a4 = *(const float4*)(Ap + 4 * q);
            unsigned h0, l0, h1, l1;
            split_pack(a4.x, a4.y, h0, l0);
            split_pack(a4.z, a4.w, h1, l1);
            int kp = (ak0 >> 1) + 2 * q;
            As_h[am][kp] = h0;     As_l[am][kp] = l0;
            As_h[am][kp + 1] = h1; As_l[am][kp + 1] = l1;
        }
        const float* Bp0 = B + (size_t)(k0 + 2 * bkp) * N + n0 + bn8;
        const float* Bp1 = Bp0 + N;
#pragma unroll
        for (int q = 0; q < 2; q++) {
            float4 b0 = *(const float4*)(Bp0 + 4 * q);
            float4 b1 = *(const float4*)(Bp1 + 4 * q);
            unsigned h, l;
            split_pack(b0.x, b1.x, h, l); Bs_h[bkp][bn8 + 4 * q + 0] = h; Bs_l[bkp][bn8 + 4 * q + 0] = l;
            split_pack(b0.y, b1.y, h, l); Bs_h[bkp][bn8 + 4 * q + 1] = h; Bs_l[bkp][bn8 + 4 * q + 1] = l;
            split_pack(b0.z, b1.z, h, l); Bs_h[bkp][bn8 + 4 * q + 2] = h; Bs_l[bkp][bn8 + 4 * q + 2] = l;
            split_pack(b0.w, b1.w, h, l); Bs_h[bkp][bn8 + 4 * q + 3] = h; Bs_l[bkp][bn8 + 4 * q + 3] = l;
        }
        __syncthreads();

#pragma unroll
        for (int kk = 0; kk < 2; kk++) {
            unsigned ah[2][4], al[2][4];
#pragma unroll
            for (int mi = 0; mi < 2; mi++) {
                int rb = wm * 32 + mi * 16;
                ah[mi][0] = As_h[rb + g][kk * 8 + c];
                ah[mi][1] = As_h[rb + g + 8][kk * 8 + c];
                ah[mi][2] = As_h[rb + g][kk * 8 + c + 4];
                ah[mi][3] = As_h[rb + g + 8][kk * 8 + c + 4];
                al[mi][0] = As_l[rb + g][kk * 8 + c];
                al[mi][1] = As_l[rb + g + 8][kk * 8 + c];
                al[mi][2] = As_l[rb + g][kk * 8 + c + 4];
                al[mi][3] = As_l[rb + g + 8][kk * 8 + c + 4];
            }
#pragma unroll
            for (int ni = 0; ni < 8; ni++) {
                int nb = wn * 64 + ni * 8 + g;
                unsigned bh[2], bl[2];
                bh[0] = Bs_h[kk * 8 + c][nb];
                bh[1] = Bs_h[kk * 8 + c + 4][nb];
                bl[0] = Bs_l[kk * 8 + c][nb];
                bl[1] = Bs_l[kk * 8 + c + 4][nb];
#pragma unroll
                for (int mi = 0; mi < 2; mi++) {
                    mma_bf16(acc[mi][ni], ah[mi], bh);
                    mma_bf16(acc[mi][ni], ah[mi], bl);
                    mma_bf16(acc[mi][ni], al[mi], bh);
                }
            }
        }
        __syncthreads();
    }

#pragma unroll
    for (int mi = 0; mi < 2; mi++) {
#pragma unroll
        for (int ni = 0; ni < 8; ni++) {
            int col = n0 + wn * 64 + ni * 8 + 2 * c;
            float2 bb = *(const float2*)(bias + col);
            int row0 = m0 + wm * 32 + mi * 16 + g;
            float2 c0 = make_float2(acc[mi][ni][0] + bb.x, acc[mi][ni][1] + bb.y);
            float2 c1 = make_float2(acc[mi][ni][2] + bb.x, acc[mi][ni][3] + bb.y);
            *(float2*)(C + (size_t)row0 * N + col) = c0;
            *(float2*)(C + (size_t)(row0 + 8) * N + col) = c1;
        }
    }
}

__global__ __launch_bounds__(256, 2)
void bf16_gemm_qkv_kernel(const float* __restrict__ x,
                          const float* __restrict__ Wqkv,
                          const float* __restrict__ bqkv) {
    bf16_gemm_bias_body(3 * DIM, DIM, x, Wqkv, bqkv, g_qkv);
}

__global__ __launch_bounds__(256, 2)
void bf16_gemm_out_kernel(const float* __restrict__ Wo,
                          const float* __restrict__ bo) {
    bf16_gemm_bias_body(DIM, DIM, g_O, Wo, bo, g_att);
}

// ---------------- causal flash attention, BF16x3 tensor cores -----------
// Block: 128 queries of one head, 8 warps, 16 queries/warp, key tiles KT=32.
// K as packed bf16x2 dim-pairs [key][36]; V as bf16 rows [key][72] read via
// ldmatrix.x4.trans. P C-frag -> A-frag needs only packing (no shuffles).
__global__ __launch_bounds__(256, 2)
void flash_bf16_kernel() {
    __shared__ unsigned Kh[KT][36], Kl[KT][36];          // [key][dim-pair]
    __shared__ __nv_bfloat16 Vh[KT][72], Vl[KT][72];     // [key][dim], stride 72

    int h = blockIdx.y;
    int m0 = blockIdx.x * 128;
    int tid = threadIdx.x;
    int w = tid >> 5, lane = tid & 31;
    int g = lane >> 2, c = lane & 3;
    int q0w = m0 + w * 16;

    // ---- Q fragments (pre-scaled by 1/8), bf16 hi/lo, in regs ----
    unsigned qh[4][4], ql[4][4];
    {
        const float* Qb = g_Q + ((size_t)h * SEQ + q0w) * HD;
#pragma unroll
        for (int kk = 0; kk < 4; kk++) {
            float2 p0 = *(const float2*)(Qb + (size_t)g * HD + kk * 16 + 2 * c);
            float2 p1 = *(const float2*)(Qb + (size_t)(g + 8) * HD + kk * 16 + 2 * c);
            float2 p2 = *(const float2*)(Qb + (size_t)g * HD + kk * 16 + 2 * c + 8);
            float2 p3 = *(const float2*)(Qb + (size_t)(g + 8) * HD + kk * 16 + 2 * c + 8);
            split_pack(p0.x * 0.125f, p0.y * 0.125f, qh[kk][0], ql[kk][0]);
            split_pack(p1.x * 0.125f, p1.y * 0.125f, qh[kk][1], ql[kk][1]);
            split_pack(p2.x * 0.125f, p2.y * 0.125f, qh[kk][2], ql[kk][2]);
            split_pack(p3.x * 0.125f, p3.y * 0.125f, qh[kk][3], ql[kk][3]);
        }
    }

    // ldmatrix base addresses (lane-dependent)
    unsigned vh_addr = (unsigned)__cvta_generic_to_shared(&Vh[lane & 15][(lane >> 4) * 8]);
    unsigned vl_addr = (unsigned)__cvta_generic_to_shared(&Vl[lane & 15][(lane >> 4) * 8]);

    float o[8][4];
#pragma unroll
    for (int nn = 0; nn < 8; nn++)
#pragma unroll
        for (int i = 0; i < 4; i++) o[nn][i] = 0.f;
    float mrow[2] = {-INFINITY, -INFINITY};
    float lrow[2] = {0.f, 0.f};

    int key = tid >> 3, dg = tid & 7;   // loader assignment: key row, 8-dim group

    int nT = (m0 + 128) / KT;
    for (int t = 0; t < nT; t++) {
        int kt0 = t * KT;
        __syncthreads();   // previous tile fully consumed

        // ---- cooperative K/V load + bf16 hi/lo split ----
        {
            const float* Kg = g_K + ((size_t)h * SEQ + kt0 + key) * HD + dg * 8;
            const float* Vg = g_V + ((size_t)h * SEQ + kt0 + key) * HD + dg * 8;
#pragma unroll
            for (int r = 0; r < 2; r++) {
                float4 kv = *(const float4*)(Kg + 4 * r);
                unsigned h0, l0, h1, l1;
                split_pack(kv.x, kv.y, h0, l0);
                split_pack(kv.z, kv.w, h1, l1);
                Kh[key][dg * 4 + 2 * r] = h0;     Kl[key][dg * 4 + 2 * r] = l0;
                Kh[key][dg * 4 + 2 * r + 1] = h1; Kl[key][dg * 4 + 2 * r + 1] = l1;

                float4 vv = *(const float4*)(Vg + 4 * r);
                split_pack(vv.x, vv.y, h0, l0);
                split_pack(vv.z, vv.w, h1, l1);
                *(unsigned*)&Vh[key][dg * 8 + 4 * r] = h0;
                *(unsigned*)&Vl[key][dg * 8 + 4 * r] = l0;
                *(unsigned*)&Vh[key][dg * 8 + 4 * r + 2] = h1;
                *(unsigned*)&Vl[key][dg * 8 + 4 * r + 2] = l1;
            }
        }
        __syncthreads();

        if (kt0 <= q0w + 15) {   // warp-level causal tile skip
            // ---- S = Q @ K^T (bf16x3) ----
            float s[4][4];
#pragma unroll
            for (int nn = 0; nn < 4; nn++)
#pragma unroll
                for (int i = 0; i < 4; i++) s[nn][i] = 0.f;
#pragma unroll
            for (int kk = 0; kk < 4; kk++) {
#pragma unroll
                for (int nn = 0; nn < 4; nn++) {
                    unsigned bh[2], bl[2];
                    bh[0] = Kh[nn * 8 + g][kk * 8 + c];
                    bh[1] = Kh[nn * 8 + g][kk * 8 + c + 4];
                    bl[0] = Kl[nn * 8 + g][kk * 8 + c];
                    bl[1] = Kl[nn * 8 + g][kk * 8 + c + 4];
                    mma_bf16(s[nn], qh[kk], bh);
                    mma_bf16(s[nn], qh[kk], bl);
                    mma_bf16(s[nn], ql[kk], bh);
                }
            }

            // ---- causal mask + online softmax ----
            float tmax[2] = {-INFINITY, -INFINITY};
#pragma unroll
            for (int nn = 0; nn < 4; nn++) {
#pragma unroll
                for (int i = 0; i < 4; i++) {
                    int qrow = q0w + g + ((i >> 1) << 3);
                    int kcol = kt0 + nn * 8 + 2 * c + (i & 1);
                    if (kcol > qrow) s[nn][i] = -INFINITY;
                    tmax[i >> 1] = fmaxf(tmax[i >> 1], s[nn][i]);
                }
            }
#pragma unroll
            for (int off = 1; off <= 2; off <<= 1) {
                tmax[0] = fmaxf(tmax[0], __shfl_xor_sync(0xffffffffu, tmax[0], off));
                tmax[1] = fmaxf(tmax[1], __shfl_xor_sync(0xffffffffu, tmax[1], off));
            }
            float mnew0 = fmaxf(mrow[0], tmax[0]);
            float mnew1 = fmaxf(mrow[1], tmax[1]);
            float corr0 = __expf(mrow[0] - mnew0);
            float corr1 = __expf(mrow[1] - mnew1);
            mrow[0] = mnew0; mrow[1] = mnew1;

            float rsum[2] = {0.f, 0.f};
#pragma unroll
            for (int nn = 0; nn < 4; nn++) {
#pragma unroll
                for (int i = 0; i < 4; i++) {
                    float p = __expf(s[nn][i] - ((i >> 1) ? mnew1 : mnew0));
                    s[nn][i] = p;
                    rsum[i >> 1] += p;
                }
            }
#pragma unroll
            for (int off = 1; off <= 2; off <<= 1) {
                rsum[0] += __shfl_xor_sync(0xffffffffu, rsum[0], off);
                rsum[1] += __shfl_xor_sync(0xffffffffu, rsum[1], off);
            }
            lrow[0] = lrow[0] * corr0 + rsum[0];
            lrow[1] = lrow[1] * corr1 + rsum[1];
#pragma unroll
            for (int nn = 0; nn < 8; nn++) {
                o[nn][0] *= corr0; o[nn][1] *= corr0;
                o[nn][2] *= corr1; o[nn][3] *= corr1;
            }

            // ---- O += P @ V (bf16x3); C-frag pairs pack directly to A-frag ----
#pragma unroll
            for (int kk = 0; kk < 2; kk++) {
                unsigned ah[4], al[4];
                split_pack(s[2 * kk][0],     s[2 * kk][1],     ah[0], al[0]);
                split_pack(s[2 * kk][2],     s[2 * kk][3],     ah[1], al[1]);
                split_pack(s[2 * kk + 1][0], s[2 * kk + 1][1], ah[2], al[2]);
                split_pack(s[2 * kk + 1][2], s[2 * kk + 1][3], ah[3], al[3]);
#pragma unroll
                for (int np = 0; np < 4; np++) {
                    unsigned bh4[4], bl4[4];
                    unsigned off = kk * (16 * 144) + np * 32;
                    ldsm_x4_trans(bh4[0], bh4[1], bh4[2], bh4[3], vh_addr + off);
                    ldsm_x4_trans(bl4[0], bl4[1], bl4[2], bl4[3], vl_addr + off);
                    mma_bf16(o[np * 2],     ah, bh4);
                    mma_bf16(o[np * 2],     ah, bl4);
                    mma_bf16(o[np * 2],     al, bh4);
                    mma_bf16(o[np * 2 + 1], ah, bh4 + 2);
                    mma_bf16(o[np * 2 + 1], ah, bl4 + 2);
                    mma_bf16(o[np * 2 + 1], al, bh4 + 2);
                }
            }
        }
    }

    // ---- normalize + write O ----
    float inv0 = 1.f / lrow[0];
    float inv1 = 1.f / lrow[1];
#pragma unroll
    for (int nn = 0; nn < 8; nn++) {
        int d = h * HD + nn * 8 + 2 * c;
        float2 r0 = make_float2(o[nn][0] * inv0, o[nn][1] * inv0);
        float2 r1 = make_float2(o[nn][2] * inv1, o[nn][3] * inv1);
        *(float2*)(g_O + (size_t)(q0w + g) * DIM + d) = r0;
        *(float2*)(g_O + (size_t)(q0w + g + 8) * DIM + d) = r1;
    }
}

// ---------------- LayerNorm over last dim (1024) ------------------------
__global__ __launch_bounds__(256)
void layernorm_kernel(const float* __restrict__ gamma,
                      const float* __restrict__ beta,
                      float* __restrict__ Y) {
    int r = blockIdx.x;
    const float* x = g_att + (size_t)r * DIM;
    int tid = threadIdx.x;

    float s = 0.f, s2 = 0.f;
#pragma unroll
    for (int it = 0; it < DIM / 256; it++) {
        float v = x[tid + it * 256];
        s += v;
        s2 += v * v;
    }
#pragma unroll
    for (int off = 16; off; off >>= 1) {
        s  += __shfl_xor_sync(0xffffffffu, s, off);
        s2 += __shfl_xor_sync(0xffffffffu, s2, off);
    }
    __shared__ float ws[8], ws2[8];
    int w = tid >> 5, lane = tid & 31;
    if (lane == 0) { ws[w] = s; ws2[w] = s2; }
    __syncthreads();
    float S1 = 0.f, S2 = 0.f;
#pragma unroll
    for (int i = 0; i < 8; i++) { S1 += ws[i]; S2 += ws2[i]; }

    float mu  = S1 * (1.f / DIM);
    float var = S2 * (1.f / DIM) - mu * mu;
    float inv = rsqrtf(var + 1e-5f);
#pragma unroll
    for (int it = 0; it < DIM / 256; it++) {
        int j = tid + it * 256;
        float v = x[j];
        Y[(size_t)r * DIM + j] = (v - mu) * inv * gamma[j] + beta[j];
    }
}

// ---------------- launch (pure kernel launches, no runtime API) ---------
extern "C" void kernel_launch(void* const* d_in, const int* in_sizes, int n_in,
                              void* d_out, int out_size) {
    const float* x     = (const float*)d_in[0];
    const float* Wqkv  = (const float*)d_in[1];
    const float* bqkv  = (const float*)d_in[2];
    const float* Wo    = (const float*)d_in[3];
    const float* bo    = (const float*)d_in[4];
    const float* gamma = (const float*)d_in[5];
    const float* beta  = (const float*)d_in[6];
    float* out = (float*)d_out;

    rope_invf_kernel<<<2, 256>>>();
    rope_tables_kernel<<<(SEQ * 512) / 256, 256>>>();
    bf16_gemm_qkv_kernel<<<dim3(3 * DIM / 128, SEQ / 128), 256>>>(x, Wqkv, bqkv);
    rope_scatter_kernel<<<(SEQ * DIM) / 256, 256>>>();
    flash_bf16_kernel<<<dim3(SEQ / 128, NH), 256>>>();
    bf16_gemm_out_kernel<<<dim3(DIM / 128, SEQ / 128), 256>>>(Wo, bo);
    layernorm_kernel<<<SEQ, 256>>>(gamma, beta, out);
}

// round 10
// speedup vs baseline: 2.1164x; 1.1017x over previous
#include <cuda_runtime.h>
#include <cuda_bf16.h>
#include <math.h>

#define SEQ 4096
#define DIM 1024
#define NH  16
#define HD  64
#define KT  32   // keys per flash tile

// ---------------- device scratch (no allocation allowed) ----------------
__device__ float g_qkv[SEQ * 3 * DIM];     // QKV projection output
__device__ float g_Q[NH * SEQ * HD];       // roped Q, head-major, fp32
// K/V pre-split to bf16 hi/lo, head-major (uint4 arrays for 16B alignment)
__device__ uint4 g_Kh4[NH * SEQ * HD / 8];
__device__ uint4 g_Kl4[NH * SEQ * HD / 8];
__device__ uint4 g_Vh4[NH * SEQ * HD / 8];
__device__ uint4 g_Vl4[NH * SEQ * HD / 8];
__device__ float g_O[SEQ * DIM];           // attention output (s, dim)
__device__ float g_att[SEQ * DIM];         // after out-proj, pre-LN
__device__ float g_cos[SEQ * 512];
__device__ float g_sin[SEQ * 512];
__device__ float g_invf[512];

// ---------------- BF16 helpers ------------------------------------------
__device__ __forceinline__ void mma_bf16(float* c, const unsigned* a, const unsigned* b) {
    asm volatile(
        "mma.sync.aligned.m16n8k16.row.col.f32.bf16.bf16.f32 "
        "{%0,%1,%2,%3}, {%4,%5,%6,%7}, {%8,%9}, {%0,%1,%2,%3};"
        : "+f"(c[0]), "+f"(c[1]), "+f"(c[2]), "+f"(c[3])
        : "r"(a[0]), "r"(a[1]), "r"(a[2]), "r"(a[3]), "r"(b[0]), "r"(b[1]));
}
__device__ __forceinline__ void split_pack(float a, float b, unsigned& h, unsigned& l) {
    __nv_bfloat16 ah = __float2bfloat16_rn(a);
    __nv_bfloat16 bh = __float2bfloat16_rn(b);
    float ar = a - __bfloat162float(ah);
    float br = b - __bfloat162float(bh);
    __nv_bfloat162 hv; hv.x = ah; hv.y = bh;
    __nv_bfloat162 lv = __floats2bfloat162_rn(ar, br);
    h = *reinterpret_cast<unsigned*>(&hv);
    l = *reinterpret_cast<unsigned*>(&lv);
}
__device__ __forceinline__ void ldsm_x4_trans(unsigned& r0, unsigned& r1,
                                              unsigned& r2, unsigned& r3, unsigned addr) {
    asm volatile("ldmatrix.sync.aligned.m8n8.x4.trans.shared.b16 {%0,%1,%2,%3}, [%4];"
                 : "=r"(r0), "=r"(r1), "=r"(r2), "=r"(r3) : "r"(addr));
}
__device__ __forceinline__ void ldsm_x4(unsigned& r0, unsigned& r1,
                                        unsigned& r2, unsigned& r3, unsigned addr) {
    asm volatile("ldmatrix.sync.aligned.m8n8.x4.shared.b16 {%0,%1,%2,%3}, [%4];"
                 : "=r"(r0), "=r"(r1), "=r"(r2), "=r"(r3) : "r"(addr));
}

// ---------------- RoPE tables -------------------------------------------
__global__ void rope_invf_kernel() {
    int i = blockIdx.x * blockDim.x + threadIdx.x;
    if (i < 512)
        g_invf[i] = (float)exp(-((double)i) * (9.210340371976184 / 512.0));
}
__global__ void rope_tables_kernel() {
    int idx = blockIdx.x * blockDim.x + threadIdx.x;
    if (idx >= SEQ * 512) return;
    int s = idx >> 9;
    int i = idx & 511;
    float ang = (float)s * g_invf[i];
    double a = (double)ang;
    double k = rint(a * 0.15915494309189535);
    float r = (float)(a - k * 6.283185307179586);
    g_cos[idx] = cosf(r);
    g_sin[idx] = sinf(r);
}

// ---------------- RoPE apply + head-major scatter + bf16 hi/lo split ----
__global__ void rope_scatter_kernel() {
    int idx = blockIdx.x * blockDim.x + threadIdx.x;   // SEQ*DIM threads
    int s = idx >> 10;
    int j = idx & 1023;
    int i = j & 511;
    float c  = g_cos[(s << 9) + i];
    float sn = g_sin[(s << 9) + i];
    const float* row = g_qkv + (size_t)s * (3 * DIM);
    float q = row[j];
    float k = row[DIM + j];
    float v = row[2 * DIM + j];
    float q2, k2;
    if (j < 512) { q2 = -row[j + 512];       k2 = -row[DIM + j + 512]; }
    else         { q2 =  row[j - 512];       k2 =  row[DIM + j - 512]; }
    float qo = q * c + q2 * sn;
    float ko = k * c + k2 * sn;
    int h = j >> 6, d = j & 63;
    int o = ((h * SEQ) + s) * HD + d;
    g_Q[o] = qo;
    __nv_bfloat16 kh = __float2bfloat16_rn(ko);
    ((__nv_bfloat16*)g_Kh4)[o] = kh;
    ((__nv_bfloat16*)g_Kl4)[o] = __float2bfloat16_rn(ko - __bfloat162float(kh));
    __nv_bfloat16 vh = __float2bfloat16_rn(v);
    ((__nv_bfloat16*)g_Vh4)[o] = vh;
    ((__nv_bfloat16*)g_Vl4)[o] = __float2bfloat16_rn(v - __bfloat162float(vh));
}

// ---------------- BF16x3 tensor-core GEMM: C = A@B + bias (unchanged) ---
__device__ __forceinline__
void bf16_gemm_bias_body(int N, int K,
                         const float* __restrict__ A,
                         const float* __restrict__ B,
                         const float* __restrict__ bias,
                         float* __restrict__ C) {
    __shared__ unsigned As_h[128][20], As_l[128][20];
    __shared__ unsigned Bs_h[16][136], Bs_l[16][136];

    int tid = threadIdx.x;
    int w = tid >> 5, lane = tid & 31;
    int g = lane >> 2, c = lane & 3;
    int m0 = blockIdx.y * 128, n0 = blockIdx.x * 128;
    int wm = w >> 1, wn = w & 1;

    float acc[2][8][4];
#pragma unroll
    for (int mi = 0; mi < 2; mi++)
#pragma unroll
        for (int ni = 0; ni < 8; ni++)
#pragma unroll
            for (int i = 0; i < 4; i++) acc[mi][ni][i] = 0.f;

    int am = tid >> 1, ak0 = (tid & 1) * 16;
    int bkp = tid >> 4, bn8 = (tid & 15) * 8;

    for (int k0 = 0; k0 < K; k0 += 32) {
        const float* Ap = A + (size_t)(m0 + am) * K + k0 + ak0;
#pragma unroll
        for (int q = 0; q < 4; q++) {
            float4 a4 = *(const float4*)(Ap + 4 * q);
            unsigned h0, l0, h1, l1;
            split_pack(a4.x, a4.y, h0, l0);
            split_pack(a4.z, a4.w, h1, l1);
            int kp = (ak0 >> 1) + 2 * q;
            As_h[am][kp] = h0;     As_l[am][kp] = l0;
            As_h[am][kp + 1] = h1; As_l[am][kp + 1] = l1;
        }
        const float* Bp0 = B + (size_t)(k0 + 2 * bkp) * N + n0 + bn8;
        const float* Bp1 = Bp0 + N;
#pragma unroll
        for (int q = 0; q < 2; q++) {
            float4 b0 = *(const float4*)(Bp0 + 4 * q);
            float4 b1 = *(const float4*)(Bp1 + 4 * q);
            unsigned h, l;
            split_pack(b0.x, b1.x, h, l); Bs_h[bkp][bn8 + 4 * q + 0] = h; Bs_l[bkp][bn8 + 4 * q + 0] = l;
            split_pack(b0.y, b1.y, h, l); Bs_h[bkp][bn8 + 4 * q + 1] = h; Bs_l[bkp][bn8 + 4 * q + 1] = l;
            split_pack(b0.z, b1.z, h, l); Bs_h[bkp][bn8 + 4 * q + 2] = h; Bs_l[bkp][bn8 + 4 * q + 2] = l;
            split_pack(b0.w, b1.w, h, l); Bs_h[bkp][bn8 + 4 * q + 3] = h; Bs_l[bkp][bn8 + 4 * q + 3] = l;
        }
        __syncthreads();

#pragma unroll
        for (int kk = 0; kk < 2; kk++) {
            unsigned ah[2][4], al[2][4];
#pragma unroll
            for (int mi = 0; mi < 2; mi++) {
                int rb = wm * 32 + mi * 16;
                ah[mi][0] = As_h[rb + g][kk * 8 + c];
                ah[mi][1] = As_h[rb + g + 8][kk * 8 + c];
                ah[mi][2] = As_h[rb + g][kk * 8 + c + 4];
                ah[mi][3] = As_h[rb + g + 8][kk * 8 + c + 4];
                al[mi][0] = As_l[rb + g][kk * 8 + c];
                al[mi][1] = As_l[rb + g + 8][kk * 8 + c];
                al[mi][2] = As_l[rb + g][kk * 8 + c + 4];
                al[mi][3] = As_l[rb + g + 8][kk * 8 + c + 4];
            }
#pragma unroll
            for (int ni = 0; ni < 8; ni++) {
                int nb = wn * 64 + ni * 8 + g;
                unsigned bh[2], bl[2];
                bh[0] = Bs_h[kk * 8 + c][nb];
                bh[1] = Bs_h[kk * 8 + c + 4][nb];
                bl[0] = Bs_l[kk * 8 + c][nb];
                bl[1] = Bs_l[kk * 8 + c + 4][nb];
#pragma unroll
                for (int mi = 0; mi < 2; mi++) {
                    mma_bf16(acc[mi][ni], ah[mi], bh);
                    mma_bf16(acc[mi][ni], ah[mi], bl);
                    mma_bf16(acc[mi][ni], al[mi], bh);
                }
            }
        }
        __syncthreads();
    }

#pragma unroll
    for (int mi = 0; mi < 2; mi++) {
#pragma unroll
        for (int ni = 0; ni < 8; ni++) {
            int col = n0 + wn * 64 + ni * 8 + 2 * c;
            float2 bb = *(const float2*)(bias + col);
            int row0 = m0 + wm * 32 + mi * 16 + g;
            float2 c0 = make_float2(acc[mi][ni][0] + bb.x, acc[mi][ni][1] + bb.y);
            float2 c1 = make_float2(acc[mi][ni][2] + bb.x, acc[mi][ni][3] + bb.y);
            *(float2*)(C + (size_t)row0 * N + col) = c0;
            *(float2*)(C + (size_t)(row0 + 8) * N + col) = c1;
        }
    }
}

__global__ __launch_bounds__(256, 2)
void bf16_gemm_qkv_kernel(const float* __restrict__ x,
                          const float* __restrict__ Wqkv,
                          const float* __restrict__ bqkv) {
    bf16_gemm_bias_body(3 * DIM, DIM, x, Wqkv, bqkv, g_qkv);
}

__global__ __launch_bounds__(256, 2)
void bf16_gemm_out_kernel(const float* __restrict__ Wo,
                          const float* __restrict__ bo) {
    bf16_gemm_bias_body(DIM, DIM, g_O, Wo, bo, g_att);
}

// ---------------- causal flash attention, BF16x3 tensor cores -----------
// 128 queries/block, 8 warps. K/V pre-split bf16 hi/lo in global; loader is
// a pure 16B copy with register prefetch of the next tile. K fragments via
// ldmatrix.x4 (rows [key][72] bf16, conflict-free), V via ldmatrix.x4.trans.
__global__ __launch_bounds__(256, 2)
void flash_bf16_kernel() {
    __shared__ __align__(16) __nv_bfloat16 Kh[KT][72], Kl[KT][72];
    __shared__ __align__(16) __nv_bfloat16 Vh[KT][72], Vl[KT][72];

    int h = blockIdx.y;
    int m0 = blockIdx.x * 128;
    int tid = threadIdx.x;
    int w = tid >> 5, lane = tid & 31;
    int g = lane >> 2, c = lane & 3;
    int q0w = m0 + w * 16;

    // ---- Q fragments (pre-scaled by 1/8), bf16 hi/lo, in regs ----
    unsigned qh[4][4], ql[4][4];
    {
        const float* Qb = g_Q + ((size_t)h * SEQ + q0w) * HD;
#pragma unroll
        for (int kk = 0; kk < 4; kk++) {
            float2 p0 = *(const float2*)(Qb + (size_t)g * HD + kk * 16 + 2 * c);
            float2 p1 = *(const float2*)(Qb + (size_t)(g + 8) * HD + kk * 16 + 2 * c);
            float2 p2 = *(const float2*)(Qb + (size_t)g * HD + kk * 16 + 2 * c + 8);
            float2 p3 = *(const float2*)(Qb + (size_t)(g + 8) * HD + kk * 16 + 2 * c + 8);
            split_pack(p0.x * 0.125f, p0.y * 0.125f, qh[kk][0], ql[kk][0]);
            split_pack(p1.x * 0.125f, p1.y * 0.125f, qh[kk][1], ql[kk][1]);
            split_pack(p2.x * 0.125f, p2.y * 0.125f, qh[kk][2], ql[kk][2]);
            split_pack(p3.x * 0.125f, p3.y * 0.125f, qh[kk][3], ql[kk][3]);
        }
    }

    // ldmatrix lane bases
    int mrow = ((lane >> 4) & 1) * 8 + (lane & 7);   // K (non-trans)
    int mcol = ((lane >> 3) & 1) * 8;
    unsigned kh_base = (unsigned)__cvta_generic_to_shared(&Kh[mrow][mcol]);
    unsigned kl_base = (unsigned)__cvta_generic_to_shared(&Kl[mrow][mcol]);
    unsigned vh_base = (unsigned)__cvta_generic_to_shared(&Vh[lane & 15][(lane >> 4) * 8]);
    unsigned vl_base = (unsigned)__cvta_generic_to_shared(&Vl[lane & 15][(lane >> 4) * 8]);

    float o[8][4];
#pragma unroll
    for (int nn = 0; nn < 8; nn++)
#pragma unroll
        for (int i = 0; i < 4; i++) o[nn][i] = 0.f;
    float mrw[2] = {-INFINITY, -INFINITY};
    float lrw[2] = {0.f, 0.f};

    // loader assignment + prefetch of tile 0
    int key = tid >> 3, dg = tid & 7;
    size_t lbase = ((size_t)h * SEQ + key) * (HD / 8) + dg;   // in uint4 units
    uint4 pkh = g_Kh4[lbase], pkl = g_Kl4[lbase];
    uint4 pvh = g_Vh4[lbase], pvl = g_Vl4[lbase];

    int nT = (m0 + 128) / KT;
    for (int t = 0; t < nT; t++) {
        int kt0 = t * KT;
        __syncthreads();   // previous tile fully consumed

        *(uint4*)&Kh[key][dg * 8] = pkh;
        *(uint4*)&Kl[key][dg * 8] = pkl;
        *(uint4*)&Vh[key][dg * 8] = pvh;
        *(uint4*)&Vl[key][dg * 8] = pvl;
        __syncthreads();

        if (t + 1 < nT) {   // prefetch next tile into regs (hides latency)
            size_t roff = lbase + (size_t)(kt0 + KT) * (HD / 8);
            pkh = g_Kh4[roff]; pkl = g_Kl4[roff];
            pvh = g_Vh4[roff]; pvl = g_Vl4[roff];
        }

        if (kt0 <= q0w + 15) {   // warp-level causal tile skip
            // ---- S = Q @ K^T (bf16x3), K frags via ldmatrix ----
            float s[4][4];
#pragma unroll
            for (int nn = 0; nn < 4; nn++)
#pragma unroll
                for (int i = 0; i < 4; i++) s[nn][i] = 0.f;
#pragma unroll
            for (int kk = 0; kk < 4; kk++) {
#pragma unroll
                for (int q2 = 0; q2 < 2; q2++) {
                    unsigned bh4[4], bl4[4];
                    unsigned off = q2 * (16 * 144) + kk * 32;
                    ldsm_x4(bh4[0], bh4[1], bh4[2], bh4[3], kh_base + off);
                    ldsm_x4(bl4[0], bl4[1], bl4[2], bl4[3], kl_base + off);
                    mma_bf16(s[2 * q2],     qh[kk], bh4);
                    mma_bf16(s[2 * q2],     qh[kk], bl4);
                    mma_bf16(s[2 * q2],     ql[kk], bh4);
                    mma_bf16(s[2 * q2 + 1], qh[kk], bh4 + 2);
                    mma_bf16(s[2 * q2 + 1], qh[kk], bl4 + 2);
                    mma_bf16(s[2 * q2 + 1], ql[kk], bh4 + 2);
                }
            }

            // ---- causal mask + online softmax ----
            float tmax[2] = {-INFINITY, -INFINITY};
#pragma unroll
            for (int nn = 0; nn < 4; nn++) {
#pragma unroll
                for (int i = 0; i < 4; i++) {
                    int qrow = q0w + g + ((i >> 1) << 3);
                    int kcol = kt0 + nn * 8 + 2 * c + (i & 1);
                    if (kcol > qrow) s[nn][i] = -INFINITY;
                    tmax[i >> 1] = fmaxf(tmax[i >> 1], s[nn][i]);
                }
            }
#pragma unroll
            for (int off = 1; off <= 2; off <<= 1) {
                tmax[0] = fmaxf(tmax[0], __shfl_xor_sync(0xffffffffu, tmax[0], off));
                tmax[1] = fmaxf(tmax[1], __shfl_xor_sync(0xffffffffu, tmax[1], off));
            }
            float mnew0 = fmaxf(mrw[0], tmax[0]);
            float mnew1 = fmaxf(mrw[1], tmax[1]);
            float corr0 = __expf(mrw[0] - mnew0);
            float corr1 = __expf(mrw[1] - mnew1);
            mrw[0] = mnew0; mrw[1] = mnew1;

            float rsum[2] = {0.f, 0.f};
#pragma unroll
            for (int nn = 0; nn < 4; nn++) {
#pragma unroll
                for (int i = 0; i < 4; i++) {
                    float p = __expf(s[nn][i] - ((i >> 1) ? mnew1 : mnew0));
                    s[nn][i] = p;
                    rsum[i >> 1] += p;
                }
            }
#pragma unroll
            for (int off = 1; off <= 2; off <<= 1) {
                rsum[0] += __shfl_xor_sync(0xffffffffu, rsum[0], off);
                rsum[1] += __shfl_xor_sync(0xffffffffu, rsum[1], off);
            }
            lrw[0] = lrw[0] * corr0 + rsum[0];
            lrw[1] = lrw[1] * corr1 + rsum[1];
#pragma unroll
            for (int nn = 0; nn < 8; nn++) {
                o[nn][0] *= corr0; o[nn][1] *= corr0;
                o[nn][2] *= corr1; o[nn][3] *= corr1;
            }

            // ---- O += P @ V (bf16x3); C-frag pairs pack directly to A-frag ----
#pragma unroll
            for (int kk = 0; kk < 2; kk++) {
                unsigned ah[4], al[4];
                split_pack(s[2 * kk][0],     s[2 * kk][1],     ah[0], al[0]);
                split_pack(s[2 * kk][2],     s[2 * kk][3],     ah[1], al[1]);
                split_pack(s[2 * kk + 1][0], s[2 * kk + 1][1], ah[2], al[2]);
                split_pack(s[2 * kk + 1][2], s[2 * kk + 1][3], ah[3], al[3]);
#pragma unroll
                for (int np = 0; np < 4; np++) {
                    unsigned bh4[4], bl4[4];
                    unsigned off = kk * (16 * 144) + np * 32;
                    ldsm_x4_trans(bh4[0], bh4[1], bh4[2], bh4[3], vh_base + off);
                    ldsm_x4_trans(bl4[0], bl4[1], bl4[2], bl4[3], vl_base + off);
                    mma_bf16(o[np * 2],     ah, bh4);
                    mma_bf16(o[np * 2],     ah, bl4);
                    mma_bf16(o[np * 2],     al, bh4);
                    mma_bf16(o[np * 2 + 1], ah, bh4 + 2);
                    mma_bf16(o[np * 2 + 1], ah, bl4 + 2);
                    mma_bf16(o[np * 2 + 1], al, bh4 + 2);
                }
            }
        }
    }

    // ---- normalize + write O ----
    float inv0 = 1.f / lrw[0];
    float inv1 = 1.f / lrw[1];
#pragma unroll
    for (int nn = 0; nn < 8; nn++) {
        int d = h * HD + nn * 8 + 2 * c;
        float2 r0 = make_float2(o[nn][0] * inv0, o[nn][1] * inv0);
        float2 r1 = make_float2(o[nn][2] * inv1, o[nn][3] * inv1);
        *(float2*)(g_O + (size_t)(q0w + g) * DIM + d) = r0;
        *(float2*)(g_O + (size_t)(q0w + g + 8) * DIM + d) = r1;
    }
}

// ---------------- LayerNorm over last dim (1024) ------------------------
__global__ __launch_bounds__(256)
void layernorm_kernel(const float* __restrict__ gamma,
                      const float* __restrict__ beta,
                      float* __restrict__ Y) {
    int r = blockIdx.x;
    const float* x = g_att + (size_t)r * DIM;
    int tid = threadIdx.x;

    float s = 0.f, s2 = 0.f;
#pragma unroll
    for (int it = 0; it < DIM / 256; it++) {
        float v = x[tid + it * 256];
        s += v;
        s2 += v * v;
    }
#pragma unroll
    for (int off = 16; off; off >>= 1) {
        s  += __shfl_xor_sync(0xffffffffu, s, off);
        s2 += __shfl_xor_sync(0xffffffffu, s2, off);
    }
    __shared__ float ws[8], ws2[8];
    int w = tid >> 5, lane = tid & 31;
    if (lane == 0) { ws[w] = s; ws2[w] = s2; }
    __syncthreads();
    float S1 = 0.f, S2 = 0.f;
#pragma unroll
    for (int i = 0; i < 8; i++) { S1 += ws[i]; S2 += ws2[i]; }

    float mu  = S1 * (1.f / DIM);
    float var = S2 * (1.f / DIM) - mu * mu;
    float inv = rsqrtf(var + 1e-5f);
#pragma unroll
    for (int it = 0; it < DIM / 256; it++) {
        int j = tid + it * 256;
        float v = x[j];
        Y[(size_t)r * DIM + j] = (v - mu) * inv * gamma[j] + beta[j];
    }
}

// ---------------- launch (pure kernel launches, no runtime API) ---------
extern "C" void kernel_launch(void* const* d_in, const int* in_sizes, int n_in,
                              void* d_out, int out_size) {
    const float* x     = (const float*)d_in[0];
    const float* Wqkv  = (const float*)d_in[1];
    const float* bqkv  = (const float*)d_in[2];
    const float* Wo    = (const float*)d_in[3];
    const float* bo    = (const float*)d_in[4];
    const float* gamma = (const float*)d_in[5];
    const float* beta  = (const float*)d_in[6];
    float* out = (float*)d_out;

    rope_invf_kernel<<<2, 256>>>();
    rope_tables_kernel<<<(SEQ * 512) / 256, 256>>>();
    bf16_gemm_qkv_kernel<<<dim3(3 * DIM / 128, SEQ / 128), 256>>>(x, Wqkv, bqkv);
    rope_scatter_kernel<<<(SEQ * DIM) / 256, 256>>>();
    flash_bf16_kernel<<<dim3(SEQ / 128, NH), 256>>>();
    bf16_gemm_out_kernel<<<dim3(DIM / 128, SEQ / 128), 256>>>(Wo, bo);
    layernorm_kernel<<<SEQ, 256>>>(gamma, beta, out);
}